// round 7
// baseline (speedup 1.0000x reference)
#include <cuda_runtime.h>
#include <cuda_bf16.h>
#include <cstdint>

#define N_NODES 100000
#define N_EDGES_MAX 3300000
#define IN_DIM  256
#define OUT_DIM 128
#define ALPHA   0.1f
#define EPS     9e-15f

// ---------------- scratch (device globals; no runtime allocation) ----------
__device__ __align__(16) float g_h[(size_t)N_NODES * OUT_DIM];   // 51.2 MB
__device__ __align__(16) float g_score_l[N_NODES];
__device__ __align__(16) float g_score_r[N_NODES];
__device__ __align__(16) __nv_bfloat16 g_wt_hi[OUT_DIM * IN_DIM]; // W^T hi  [n][k]
__device__ __align__(16) __nv_bfloat16 g_wt_lo[OUT_DIM * IN_DIM]; // W^T lo
__device__ __align__(16) float g_wa_l[IN_DIM];   // W @ a_l
__device__ __align__(16) float g_wa_r[IN_DIM];   // W @ a_r
__device__ int   g_src[N_EDGES_MAX];
__device__ int   g_dst[N_EDGES_MAX];
__device__ int   g_deg[N_NODES];
__device__ int   g_rowptr[N_NODES];
__device__ int   g_cursor[N_NODES];
__device__ __align__(16) int2 g_csr[N_EDGES_MAX];   // packed (dst, w-bits)
__device__ int   g_is64;

__device__ __forceinline__ uint32_t pack2bf16(float x, float y) {
    __nv_bfloat16 hx = __float2bfloat16(x), hy = __float2bfloat16(y);
    uint16_t a = *reinterpret_cast<uint16_t*>(&hx);
    uint16_t b = *reinterpret_cast<uint16_t*>(&hy);
    return (uint32_t)a | ((uint32_t)b << 16);
}

// ---------------------------------------------------------------------------
// K0: zero degree histogram + reset dtype flag + probe dtype
// ---------------------------------------------------------------------------
__global__ void zero_probe_kernel(const void* ei, int n_elems64) {
    int i = blockIdx.x * blockDim.x + threadIdx.x;
    if (i < N_NODES) g_deg[i] = 0;
    if (i == 0) g_is64 = 1;
}
__global__ void probe_kernel(const void* ei, int n_elems64) {
    const long long* p = (const long long*)ei;
    int i = threadIdx.x + blockIdx.x * blockDim.x;
    int K = n_elems64 < 4096 ? n_elems64 : 4096;
    if (i < K) {
        long long v = p[i];
        if (v < 0 || v >= N_NODES) atomicAnd(&g_is64, 0);
    }
}

// K2: convert edge list + histogram degrees by src
__global__ __launch_bounds__(256) void convert_hist_kernel(const void* __restrict__ ei_raw,
                                                           const int n_edges) {
    int i = blockIdx.x * blockDim.x + threadIdx.x;
    if (i >= n_edges) return;
    int src, dst;
    if (g_is64) {
        const long long* ei = (const long long*)ei_raw;
        src = (int)ei[i];
        dst = (int)ei[(size_t)n_edges + i];
    } else {
        const int* ei = (const int*)ei_raw;
        src = ei[i];
        dst = ei[(size_t)n_edges + i];
    }
    g_src[i] = src;
    g_dst[i] = dst;
    if ((unsigned)src < N_NODES && (unsigned)dst < N_NODES)
        atomicAdd(&g_deg[src], 1);
}

// K3: W^T split into bf16 hi/lo  (Wt[n][k] = W[k][n])
__global__ __launch_bounds__(256) void prep_w_kernel(const float* __restrict__ W) {
    int i = blockIdx.x * blockDim.x + threadIdx.x;
    if (i >= IN_DIM * OUT_DIM) return;
    int n = i % OUT_DIM;
    int k = i / OUT_DIM;
    float w = W[(size_t)k * OUT_DIM + n];
    __nv_bfloat16 hi = __float2bfloat16(w);
    float lo = w - __bfloat162float(hi);
    g_wt_hi[(size_t)n * IN_DIM + k] = hi;
    g_wt_lo[(size_t)n * IN_DIM + k] = __float2bfloat16(lo);
}

// K3b: Wa vectors: g_wa_l[k] = sum_n W[k][n]*attn[n],  g_wa_r with attn[128+n]
__global__ __launch_bounds__(256) void prep_wa_kernel(const float* __restrict__ W,
                                                      const float* __restrict__ attn) {
    int k = blockIdx.x * blockDim.x + threadIdx.x;
    if (k >= IN_DIM) return;
    const float* wr = W + (size_t)k * OUT_DIM;
    float sl = 0.f, sr = 0.f;
    #pragma unroll 8
    for (int n = 0; n < OUT_DIM; n++) {
        float w = wr[n];
        sl += w * attn[n];
        sr += w * attn[OUT_DIM + n];
    }
    g_wa_l[k] = sl;
    g_wa_r[k] = sr;
}

// ---------------------------------------------------------------------------
// K4: mma.sync bf16 GEMM  H = X @ W  (3-term bf16 split, fp32 accum)
//     + fused scores  score = X @ (W a)
// ---------------------------------------------------------------------------
#define KCHUNK 64
#define ROW_W   72                       // bf16 per padded row
#define TILE_B  (128 * ROW_W * 2)        // 18432 bytes per tile
#define GEMM_SMEM (4 * TILE_B)

__device__ __forceinline__ void mma16816(float* c, const uint32_t* a, const uint32_t* b) {
    asm volatile(
        "mma.sync.aligned.m16n8k16.row.col.f32.bf16.bf16.f32 "
        "{%0,%1,%2,%3}, {%4,%5,%6,%7}, {%8,%9}, {%0,%1,%2,%3};"
        : "+f"(c[0]), "+f"(c[1]), "+f"(c[2]), "+f"(c[3])
        : "r"(a[0]), "r"(a[1]), "r"(a[2]), "r"(a[3]), "r"(b[0]), "r"(b[1]));
}

__global__ __launch_bounds__(256, 2)
void gemm_mma_kernel(const float* __restrict__ X) {
    extern __shared__ __align__(16) char smem_raw[];
    __nv_bfloat16* sAh = (__nv_bfloat16*)(smem_raw);
    __nv_bfloat16* sAl = (__nv_bfloat16*)(smem_raw + TILE_B);
    __nv_bfloat16* sBh = (__nv_bfloat16*)(smem_raw + 2 * TILE_B);
    __nv_bfloat16* sBl = (__nv_bfloat16*)(smem_raw + 3 * TILE_B);

    const int tid  = threadIdx.x;
    const int wid  = tid >> 5;
    const int lane = tid & 31;
    const int g    = lane >> 2;     // 0..7
    const int t    = lane & 3;      // 0..3
    const int wm   = wid >> 2;      // 0..1  (m warp)
    const int wn   = wid & 3;       // 0..3  (n warp)
    const int block_row = blockIdx.x * 128;

    float acc[4][4][4];
    #pragma unroll
    for (int i = 0; i < 4; i++)
        #pragma unroll
        for (int j = 0; j < 4; j++)
            #pragma unroll
            for (int r = 0; r < 4; r++) acc[i][j][r] = 0.f;

    float sl[4] = {0.f, 0.f, 0.f, 0.f};   // fused score partials (per u-slot)
    float sr[4] = {0.f, 0.f, 0.f, 0.f};

    for (int kc = 0; kc < IN_DIM / KCHUNK; kc++) {
        // ---- load + split X chunk (128 rows x 64 cols): 1024 units of 8 cols
        #pragma unroll
        for (int u = 0; u < 4; u++) {
            const int unit = tid + 256 * u;
            const int row  = unit >> 3;
            const int c8   = (unit & 7) * 8;
            const int gr   = block_row + row;
            float4 v0 = make_float4(0.f, 0.f, 0.f, 0.f);
            float4 v1 = make_float4(0.f, 0.f, 0.f, 0.f);
            if (gr < N_NODES) {
                const float* xp = X + (size_t)gr * IN_DIM + kc * KCHUNK + c8;
                v0 = *(const float4*)(xp);
                v1 = *(const float4*)(xp + 4);
            }
            // fused score partial: dot with Wa vectors (broadcast loads)
            {
                const float4 wl0 = *(const float4*)(g_wa_l + kc * KCHUNK + c8);
                const float4 wl1 = *(const float4*)(g_wa_l + kc * KCHUNK + c8 + 4);
                const float4 wr0 = *(const float4*)(g_wa_r + kc * KCHUNK + c8);
                const float4 wr1 = *(const float4*)(g_wa_r + kc * KCHUNK + c8 + 4);
                sl[u] += v0.x * wl0.x + v0.y * wl0.y + v0.z * wl0.z + v0.w * wl0.w
                       + v1.x * wl1.x + v1.y * wl1.y + v1.z * wl1.z + v1.w * wl1.w;
                sr[u] += v0.x * wr0.x + v0.y * wr0.y + v0.z * wr0.z + v0.w * wr0.w
                       + v1.x * wr1.x + v1.y * wr1.y + v1.z * wr1.z + v1.w * wr1.w;
            }
            uint4 hi, lo;
            {
                __nv_bfloat16 h0 = __float2bfloat16(v0.x), h1 = __float2bfloat16(v0.y);
                __nv_bfloat16 h2 = __float2bfloat16(v0.z), h3 = __float2bfloat16(v0.w);
                __nv_bfloat16 h4 = __float2bfloat16(v1.x), h5 = __float2bfloat16(v1.y);
                __nv_bfloat16 h6 = __float2bfloat16(v1.z), h7 = __float2bfloat16(v1.w);
                hi.x = ((uint32_t)*(uint16_t*)&h0) | ((uint32_t)*(uint16_t*)&h1 << 16);
                hi.y = ((uint32_t)*(uint16_t*)&h2) | ((uint32_t)*(uint16_t*)&h3 << 16);
                hi.z = ((uint32_t)*(uint16_t*)&h4) | ((uint32_t)*(uint16_t*)&h5 << 16);
                hi.w = ((uint32_t)*(uint16_t*)&h6) | ((uint32_t)*(uint16_t*)&h7 << 16);
                lo.x = pack2bf16(v0.x - __bfloat162float(h0), v0.y - __bfloat162float(h1));
                lo.y = pack2bf16(v0.z - __bfloat162float(h2), v0.w - __bfloat162float(h3));
                lo.z = pack2bf16(v1.x - __bfloat162float(h4), v1.y - __bfloat162float(h5));
                lo.w = pack2bf16(v1.z - __bfloat162float(h6), v1.w - __bfloat162float(h7));
            }
            *(uint4*)(sAh + row * ROW_W + c8) = hi;
            *(uint4*)(sAl + row * ROW_W + c8) = lo;
        }
        // ---- load B chunk (Wt hi/lo, 128 n-rows x 64 k)
        #pragma unroll
        for (int u = 0; u < 4; u++) {
            const int unit = tid + 256 * u;
            const int n    = unit >> 3;
            const int c8   = (unit & 7) * 8;
            const size_t gofs = (size_t)n * IN_DIM + kc * KCHUNK + c8;
            *(uint4*)(sBh + n * ROW_W + c8) = *(const uint4*)(g_wt_hi + gofs);
            *(uint4*)(sBl + n * ROW_W + c8) = *(const uint4*)(g_wt_lo + gofs);
        }
        __syncthreads();

        const uint32_t* Ah = (const uint32_t*)sAh;
        const uint32_t* Al = (const uint32_t*)sAl;
        const uint32_t* Bh = (const uint32_t*)sBh;
        const uint32_t* Bl = (const uint32_t*)sBl;
        const int RW = ROW_W / 2;   // 36 words per row

        #define DO_TERM(Ap, Bp)                                                        \
        {                                                                              \
            _Pragma("unroll")                                                          \
            for (int ks = 0; ks < 4; ks++) {                                           \
                uint32_t afr[4][4];                                                    \
                _Pragma("unroll")                                                      \
                for (int mt = 0; mt < 4; mt++) {                                       \
                    const int row = wm * 64 + mt * 16 + g;                             \
                    afr[mt][0] = Ap[row * RW + ks * 8 + t];                            \
                    afr[mt][1] = Ap[(row + 8) * RW + ks * 8 + t];                      \
                    afr[mt][2] = Ap[row * RW + ks * 8 + t + 4];                        \
                    afr[mt][3] = Ap[(row + 8) * RW + ks * 8 + t + 4];                  \
                }                                                                      \
                uint32_t bfr[4][2];                                                    \
                _Pragma("unroll")                                                      \
                for (int nt = 0; nt < 4; nt++) {                                       \
                    const int nr = wn * 32 + nt * 8 + g;                               \
                    bfr[nt][0] = Bp[nr * RW + ks * 8 + t];                             \
                    bfr[nt][1] = Bp[nr * RW + ks * 8 + t + 4];                         \
                }                                                                      \
                _Pragma("unroll")                                                      \
                for (int mt = 0; mt < 4; mt++)                                         \
                    _Pragma("unroll")                                                  \
                    for (int nt = 0; nt < 4; nt++)                                     \
                        mma16816(acc[mt][nt], afr[mt], bfr[nt]);                       \
            }                                                                          \
        }

        DO_TERM(Ah, Bh);
        DO_TERM(Ah, Bl);
        DO_TERM(Al, Bh);
        #undef DO_TERM
        __syncthreads();
    }

    // ---- fused score reduce: 8 threads share a row -> shfl within groups of 8
    #pragma unroll
    for (int u = 0; u < 4; u++) {
        float dl = sl[u], dr = sr[u];
        #pragma unroll
        for (int off = 4; off > 0; off >>= 1) {
            dl += __shfl_xor_sync(0xffffffff, dl, off, 8);
            dr += __shfl_xor_sync(0xffffffff, dr, off, 8);
        }
        const int unit = tid + 256 * u;
        const int row  = unit >> 3;
        const int gr   = block_row + row;
        if ((tid & 7) == 0 && gr < N_NODES) {
            g_score_l[gr] = dl;
            g_score_r[gr] = dr;
        }
    }

    // ---- epilogue: write H
    #pragma unroll
    for (int mt = 0; mt < 4; mt++) {
        const int r0 = block_row + wm * 64 + mt * 16 + g;
        const int r1 = r0 + 8;
        #pragma unroll
        for (int nt = 0; nt < 4; nt++) {
            const int col = wn * 32 + nt * 8 + 2 * t;
            if (r0 < N_NODES)
                *(float2*)(g_h + (size_t)r0 * OUT_DIM + col) = make_float2(acc[mt][nt][0], acc[mt][nt][1]);
            if (r1 < N_NODES)
                *(float2*)(g_h + (size_t)r1 * OUT_DIM + col) = make_float2(acc[mt][nt][2], acc[mt][nt][3]);
        }
    }
}

// ---------------------------------------------------------------------------
// K6: exclusive scan of degrees -> rowptr, cursor
// ---------------------------------------------------------------------------
__global__ __launch_bounds__(1024) void scan_kernel() {
    __shared__ int sh[1024];
    const int t = threadIdx.x;
    const int CHUNK = (N_NODES + 1023) / 1024;
    const int lo = t * CHUNK;
    const int hi = min(lo + CHUNK, N_NODES);

    int s = 0;
    for (int i = lo; i < hi; i++) s += g_deg[i];
    sh[t] = s;
    __syncthreads();
    for (int off = 1; off < 1024; off <<= 1) {
        int v = (t >= off) ? sh[t - off] : 0;
        __syncthreads();
        sh[t] += v;
        __syncthreads();
    }
    int run = sh[t] - s;
    for (int i = lo; i < hi; i++) {
        g_rowptr[i] = run;
        g_cursor[i] = run;
        run += g_deg[i];
    }
}

// ---------------------------------------------------------------------------
// K7: scatter edges into CSR (packed int2 record) with softmax weights
// ---------------------------------------------------------------------------
__global__ __launch_bounds__(256) void scatter_kernel(const int n_edges) {
    int i = blockIdx.x * blockDim.x + threadIdx.x;
    if (i >= n_edges) return;
    const int src = g_src[i];
    const int dst = g_dst[i];
    if ((unsigned)src >= N_NODES || (unsigned)dst >= N_NODES) return;

    float s = g_score_l[src] + g_score_r[dst];
    s = (s > 0.f) ? s : ALPHA * s;
    const float w = __expf(s);

    const int pos = atomicAdd(&g_cursor[src], 1);
    g_csr[pos] = make_int2(dst, __float_as_int(w));
}

// ---------------------------------------------------------------------------
// K8: aggregate per node (one warp per node, 4-wide unrolled gather)
// ---------------------------------------------------------------------------
__global__ __launch_bounds__(256) void aggregate_kernel(float* __restrict__ out) {
    const int node = (blockIdx.x * blockDim.x + threadIdx.x) >> 5;
    const int lane = threadIdx.x & 31;
    if (node >= N_NODES) return;

    const int start = g_rowptr[node];
    const int deg   = g_deg[node];
    const int end   = start + deg;

    float4 acc = make_float4(0.f, 0.f, 0.f, 0.f);
    float wsum = 0.f;

    int e = start;
    for (; e + 4 <= end; e += 4) {
        int2 r0 = g_csr[e], r1 = g_csr[e + 1], r2 = g_csr[e + 2], r3 = g_csr[e + 3];
        float w0 = __int_as_float(r0.y), w1 = __int_as_float(r1.y);
        float w2 = __int_as_float(r2.y), w3 = __int_as_float(r3.y);
        float4 v0 = *(const float4*)(g_h + (size_t)r0.x * OUT_DIM + lane * 4);
        float4 v1 = *(const float4*)(g_h + (size_t)r1.x * OUT_DIM + lane * 4);
        float4 v2 = *(const float4*)(g_h + (size_t)r2.x * OUT_DIM + lane * 4);
        float4 v3 = *(const float4*)(g_h + (size_t)r3.x * OUT_DIM + lane * 4);
        acc.x += w0 * v0.x + w1 * v1.x + w2 * v2.x + w3 * v3.x;
        acc.y += w0 * v0.y + w1 * v1.y + w2 * v2.y + w3 * v3.y;
        acc.z += w0 * v0.z + w1 * v1.z + w2 * v2.z + w3 * v3.z;
        acc.w += w0 * v0.w + w1 * v1.w + w2 * v2.w + w3 * v3.w;
        wsum  += w0 + w1 + w2 + w3;
    }
    for (; e < end; e++) {
        int2 r = g_csr[e];
        const float w = __int_as_float(r.y);
        float4 v = *(const float4*)(g_h + (size_t)r.x * OUT_DIM + lane * 4);
        acc.x += w * v.x; acc.y += w * v.y; acc.z += w * v.z; acc.w += w * v.w;
        wsum  += w;
    }

    const float inv = 1.0f / (wsum + EPS);
    acc.x *= inv; acc.y *= inv; acc.z *= inv; acc.w *= inv;
    acc.x = (acc.x > 0.f) ? acc.x : ALPHA * acc.x;
    acc.y = (acc.y > 0.f) ? acc.y : ALPHA * acc.y;
    acc.z = (acc.z > 0.f) ? acc.z : ALPHA * acc.z;
    acc.w = (acc.w > 0.f) ? acc.w : ALPHA * acc.w;
    *(float4*)(out + (size_t)node * OUT_DIM + lane * 4) = acc;
}

// ---------------------------------------------------------------------------
extern "C" void kernel_launch(void* const* d_in, const int* in_sizes, int n_in,
                              void* d_out, int out_size) {
    const float* x    = (const float*)d_in[0];
    const void*  ei   = d_in[1];
    const float* W    = (const float*)d_in[2];
    const float* attn = (const float*)d_in[3];
    float*       out  = (float*)d_out;

    const int n_edges = in_sizes[1] / 2;

    cudaFuncSetAttribute(gemm_mma_kernel, cudaFuncAttributeMaxDynamicSharedMemorySize, GEMM_SMEM);

    zero_probe_kernel<<<(N_NODES + 255) / 256, 256>>>(ei, in_sizes[1]);
    probe_kernel<<<16, 256>>>(ei, in_sizes[1]);
    convert_hist_kernel<<<(n_edges + 255) / 256, 256>>>(ei, n_edges);
    prep_w_kernel<<<(IN_DIM * OUT_DIM + 255) / 256, 256>>>(W);
    prep_wa_kernel<<<1, 256>>>(W, attn);
    gemm_mma_kernel<<<(N_NODES + 127) / 128, 256, GEMM_SMEM>>>(x);
    scan_kernel<<<1, 1024>>>();
    scatter_kernel<<<(n_edges + 255) / 256, 256>>>(n_edges);
    aggregate_kernel<<<(N_NODES * 32 + 255) / 256, 256>>>(out);
}

// round 8
// speedup vs baseline: 1.0540x; 1.0540x over previous
#include <cuda_runtime.h>
#include <cuda_bf16.h>
#include <cstdint>

#define N_NODES 100000
#define N_EDGES_MAX 3300000
#define IN_DIM  256
#define OUT_DIM 128
#define ALPHA   0.1f
#define EPS     9e-15f

// ---------------- scratch (device globals; no runtime allocation) ----------
__device__ __align__(16) float g_h[(size_t)N_NODES * OUT_DIM];   // 51.2 MB
__device__ __align__(16) float g_score_l[N_NODES];
__device__ __align__(16) float g_score_r[N_NODES];
__device__ __align__(16) __nv_bfloat16 g_wt_hi[OUT_DIM * IN_DIM]; // W^T hi  [n][k]
__device__ __align__(16) __nv_bfloat16 g_wt_lo[OUT_DIM * IN_DIM]; // W^T lo
__device__ int   g_src[N_EDGES_MAX];
__device__ int   g_dst[N_EDGES_MAX];
__device__ int   g_deg[N_NODES];
__device__ int   g_rowptr[N_NODES];
__device__ int   g_cursor[N_NODES];
__device__ __align__(16) int2 g_csr[N_EDGES_MAX];   // packed (dst, w-bits)
__device__ int   g_is64;

__device__ __forceinline__ uint32_t pack2bf16(float x, float y) {
    __nv_bfloat16 hx = __float2bfloat16(x), hy = __float2bfloat16(y);
    uint16_t a = *reinterpret_cast<uint16_t*>(&hx);
    uint16_t b = *reinterpret_cast<uint16_t*>(&hy);
    return (uint32_t)a | ((uint32_t)b << 16);
}

// ---------------------------------------------------------------------------
// K0: zero degree histogram + reset dtype flag
// ---------------------------------------------------------------------------
__global__ void zero_kernel() {
    int i = blockIdx.x * blockDim.x + threadIdx.x;
    if (i < N_NODES) g_deg[i] = 0;
    if (i == 0) g_is64 = 1;
}
// K1: probe dtype (int64 vs int32 delivery)
__global__ void probe_kernel(const void* ei, int n_elems64) {
    const long long* p = (const long long*)ei;
    int i = threadIdx.x + blockIdx.x * blockDim.x;
    int K = n_elems64 < 4096 ? n_elems64 : 4096;
    if (i < K) {
        long long v = p[i];
        if (v < 0 || v >= N_NODES) atomicAnd(&g_is64, 0);
    }
}

// K2: convert edge list + histogram degrees by src
__global__ __launch_bounds__(256) void convert_hist_kernel(const void* __restrict__ ei_raw,
                                                           const int n_edges) {
    int i = blockIdx.x * blockDim.x + threadIdx.x;
    if (i >= n_edges) return;
    int src, dst;
    if (g_is64) {
        const long long* ei = (const long long*)ei_raw;
        src = (int)ei[i];
        dst = (int)ei[(size_t)n_edges + i];
    } else {
        const int* ei = (const int*)ei_raw;
        src = ei[i];
        dst = ei[(size_t)n_edges + i];
    }
    g_src[i] = src;
    g_dst[i] = dst;
    if ((unsigned)src < N_NODES && (unsigned)dst < N_NODES)
        atomicAdd(&g_deg[src], 1);
}

// K3: W^T split into bf16 hi/lo  (Wt[n][k] = W[k][n])
__global__ __launch_bounds__(256) void prep_w_kernel(const float* __restrict__ W) {
    int i = blockIdx.x * blockDim.x + threadIdx.x;
    if (i >= IN_DIM * OUT_DIM) return;
    int n = i % OUT_DIM;
    int k = i / OUT_DIM;
    float w = W[(size_t)k * OUT_DIM + n];
    __nv_bfloat16 hi = __float2bfloat16(w);
    float lo = w - __bfloat162float(hi);
    g_wt_hi[(size_t)n * IN_DIM + k] = hi;
    g_wt_lo[(size_t)n * IN_DIM + k] = __float2bfloat16(lo);
}

// ---------------------------------------------------------------------------
// K4: mma.sync bf16 GEMM  H = X @ W  (3-term bf16 split, fp32 accum)
//   CTA tile 128x128, K in 4 chunks of 64.  (identical to R6 passing version)
// ---------------------------------------------------------------------------
#define KCHUNK 64
#define ROW_W   72                       // bf16 per padded row
#define TILE_B  (128 * ROW_W * 2)        // 18432 bytes per tile
#define GEMM_SMEM (4 * TILE_B)

__device__ __forceinline__ void mma16816(float* c, const uint32_t* a, const uint32_t* b) {
    asm volatile(
        "mma.sync.aligned.m16n8k16.row.col.f32.bf16.bf16.f32 "
        "{%0,%1,%2,%3}, {%4,%5,%6,%7}, {%8,%9}, {%0,%1,%2,%3};"
        : "+f"(c[0]), "+f"(c[1]), "+f"(c[2]), "+f"(c[3])
        : "r"(a[0]), "r"(a[1]), "r"(a[2]), "r"(a[3]), "r"(b[0]), "r"(b[1]));
}

__global__ __launch_bounds__(256, 2)
void gemm_mma_kernel(const float* __restrict__ X) {
    extern __shared__ __align__(16) char smem_raw[];
    __nv_bfloat16* sAh = (__nv_bfloat16*)(smem_raw);
    __nv_bfloat16* sAl = (__nv_bfloat16*)(smem_raw + TILE_B);
    __nv_bfloat16* sBh = (__nv_bfloat16*)(smem_raw + 2 * TILE_B);
    __nv_bfloat16* sBl = (__nv_bfloat16*)(smem_raw + 3 * TILE_B);

    const int tid  = threadIdx.x;
    const int wid  = tid >> 5;
    const int lane = tid & 31;
    const int g    = lane >> 2;     // 0..7
    const int t    = lane & 3;      // 0..3
    const int wm   = wid >> 2;      // 0..1  (m warp)
    const int wn   = wid & 3;       // 0..3  (n warp)
    const int block_row = blockIdx.x * 128;

    float acc[4][4][4];
    #pragma unroll
    for (int i = 0; i < 4; i++)
        #pragma unroll
        for (int j = 0; j < 4; j++)
            #pragma unroll
            for (int r = 0; r < 4; r++) acc[i][j][r] = 0.f;

    for (int kc = 0; kc < IN_DIM / KCHUNK; kc++) {
        // ---- load + split X chunk (128 rows x 64 cols): 1024 units of 8 cols
        #pragma unroll
        for (int u = 0; u < 4; u++) {
            const int unit = tid + 256 * u;
            const int row  = unit >> 3;
            const int c8   = (unit & 7) * 8;
            const int gr   = block_row + row;
            float4 v0 = make_float4(0.f, 0.f, 0.f, 0.f);
            float4 v1 = make_float4(0.f, 0.f, 0.f, 0.f);
            if (gr < N_NODES) {
                const float* xp = X + (size_t)gr * IN_DIM + kc * KCHUNK + c8;
                v0 = *(const float4*)(xp);
                v1 = *(const float4*)(xp + 4);
            }
            uint4 hi, lo;
            {
                __nv_bfloat16 h0 = __float2bfloat16(v0.x), h1 = __float2bfloat16(v0.y);
                __nv_bfloat16 h2 = __float2bfloat16(v0.z), h3 = __float2bfloat16(v0.w);
                __nv_bfloat16 h4 = __float2bfloat16(v1.x), h5 = __float2bfloat16(v1.y);
                __nv_bfloat16 h6 = __float2bfloat16(v1.z), h7 = __float2bfloat16(v1.w);
                hi.x = ((uint32_t)*(uint16_t*)&h0) | ((uint32_t)*(uint16_t*)&h1 << 16);
                hi.y = ((uint32_t)*(uint16_t*)&h2) | ((uint32_t)*(uint16_t*)&h3 << 16);
                hi.z = ((uint32_t)*(uint16_t*)&h4) | ((uint32_t)*(uint16_t*)&h5 << 16);
                hi.w = ((uint32_t)*(uint16_t*)&h6) | ((uint32_t)*(uint16_t*)&h7 << 16);
                lo.x = pack2bf16(v0.x - __bfloat162float(h0), v0.y - __bfloat162float(h1));
                lo.y = pack2bf16(v0.z - __bfloat162float(h2), v0.w - __bfloat162float(h3));
                lo.z = pack2bf16(v1.x - __bfloat162float(h4), v1.y - __bfloat162float(h5));
                lo.w = pack2bf16(v1.z - __bfloat162float(h6), v1.w - __bfloat162float(h7));
            }
            *(uint4*)(sAh + row * ROW_W + c8) = hi;
            *(uint4*)(sAl + row * ROW_W + c8) = lo;
        }
        // ---- load B chunk (Wt hi/lo, 128 n-rows x 64 k)
        #pragma unroll
        for (int u = 0; u < 4; u++) {
            const int unit = tid + 256 * u;
            const int n    = unit >> 3;
            const int c8   = (unit & 7) * 8;
            const size_t gofs = (size_t)n * IN_DIM + kc * KCHUNK + c8;
            *(uint4*)(sBh + n * ROW_W + c8) = *(const uint4*)(g_wt_hi + gofs);
            *(uint4*)(sBl + n * ROW_W + c8) = *(const uint4*)(g_wt_lo + gofs);
        }
        __syncthreads();

        const uint32_t* Ah = (const uint32_t*)sAh;
        const uint32_t* Al = (const uint32_t*)sAl;
        const uint32_t* Bh = (const uint32_t*)sBh;
        const uint32_t* Bl = (const uint32_t*)sBl;
        const int RW = ROW_W / 2;   // 36 words per row

        #define DO_TERM(Ap, Bp)                                                        \
        {                                                                              \
            _Pragma("unroll")                                                          \
            for (int ks = 0; ks < 4; ks++) {                                           \
                uint32_t afr[4][4];                                                    \
                _Pragma("unroll")                                                      \
                for (int mt = 0; mt < 4; mt++) {                                       \
                    const int row = wm * 64 + mt * 16 + g;                             \
                    afr[mt][0] = Ap[row * RW + ks * 8 + t];                            \
                    afr[mt][1] = Ap[(row + 8) * RW + ks * 8 + t];                      \
                    afr[mt][2] = Ap[row * RW + ks * 8 + t + 4];                        \
                    afr[mt][3] = Ap[(row + 8) * RW + ks * 8 + t + 4];                  \
                }                                                                      \
                uint32_t bfr[4][2];                                                    \
                _Pragma("unroll")                                                      \
                for (int nt = 0; nt < 4; nt++) {                                       \
                    const int nr = wn * 32 + nt * 8 + g;                               \
                    bfr[nt][0] = Bp[nr * RW + ks * 8 + t];                             \
                    bfr[nt][1] = Bp[nr * RW + ks * 8 + t + 4];                         \
                }                                                                      \
                _Pragma("unroll")                                                      \
                for (int mt = 0; mt < 4; mt++)                                         \
                    _Pragma("unroll")                                                  \
                    for (int nt = 0; nt < 4; nt++)                                     \
                        mma16816(acc[mt][nt], afr[mt], bfr[nt]);                       \
            }                                                                          \
        }

        DO_TERM(Ah, Bh);
        DO_TERM(Ah, Bl);
        DO_TERM(Al, Bh);
        #undef DO_TERM
        __syncthreads();
    }

    // ---- epilogue: write H
    #pragma unroll
    for (int mt = 0; mt < 4; mt++) {
        const int r0 = block_row + wm * 64 + mt * 16 + g;
        const int r1 = r0 + 8;
        #pragma unroll
        for (int nt = 0; nt < 4; nt++) {
            const int col = wn * 32 + nt * 8 + 2 * t;
            if (r0 < N_NODES)
                *(float2*)(g_h + (size_t)r0 * OUT_DIM + col) = make_float2(acc[mt][nt][0], acc[mt][nt][1]);
            if (r1 < N_NODES)
                *(float2*)(g_h + (size_t)r1 * OUT_DIM + col) = make_float2(acc[mt][nt][2], acc[mt][nt][3]);
        }
    }
}

// ---------------------------------------------------------------------------
// K5: per-node attention scores  (one warp per node)
// ---------------------------------------------------------------------------
__global__ __launch_bounds__(256) void score_kernel(const float* __restrict__ attn) {
    const int warp = (blockIdx.x * blockDim.x + threadIdx.x) >> 5;
    const int lane = threadIdx.x & 31;
    if (warp >= N_NODES) return;

    float4 hv = *(const float4*)(g_h + (size_t)warp * OUT_DIM + lane * 4);
    float4 al = *(const float4*)(attn + lane * 4);
    float4 ar = *(const float4*)(attn + OUT_DIM + lane * 4);

    float dl = hv.x * al.x + hv.y * al.y + hv.z * al.z + hv.w * al.w;
    float dr = hv.x * ar.x + hv.y * ar.y + hv.z * ar.z + hv.w * ar.w;

    #pragma unroll
    for (int off = 16; off > 0; off >>= 1) {
        dl += __shfl_xor_sync(0xffffffff, dl, off);
        dr += __shfl_xor_sync(0xffffffff, dr, off);
    }
    if (lane == 0) {
        g_score_l[warp] = dl;
        g_score_r[warp] = dr;
    }
}

// ---------------------------------------------------------------------------
// K6: exclusive scan of degrees -> rowptr, cursor
// ---------------------------------------------------------------------------
__global__ __launch_bounds__(1024) void scan_kernel() {
    __shared__ int sh[1024];
    const int t = threadIdx.x;
    const int CHUNK = (N_NODES + 1023) / 1024;
    const int lo = t * CHUNK;
    const int hi = min(lo + CHUNK, N_NODES);

    int s = 0;
    for (int i = lo; i < hi; i++) s += g_deg[i];
    sh[t] = s;
    __syncthreads();
    for (int off = 1; off < 1024; off <<= 1) {
        int v = (t >= off) ? sh[t - off] : 0;
        __syncthreads();
        sh[t] += v;
        __syncthreads();
    }
    int run = sh[t] - s;
    for (int i = lo; i < hi; i++) {
        g_rowptr[i] = run;
        g_cursor[i] = run;
        run += g_deg[i];
    }
}

// ---------------------------------------------------------------------------
// K7: scatter edges into CSR (packed int2 record) with softmax weights
// ---------------------------------------------------------------------------
__global__ __launch_bounds__(256) void scatter_kernel(const int n_edges) {
    int i = blockIdx.x * blockDim.x + threadIdx.x;
    if (i >= n_edges) return;
    const int src = g_src[i];
    const int dst = g_dst[i];
    if ((unsigned)src >= N_NODES || (unsigned)dst >= N_NODES) return;

    float s = g_score_l[src] + g_score_r[dst];
    s = (s > 0.f) ? s : ALPHA * s;
    const float w = __expf(s);

    const int pos = atomicAdd(&g_cursor[src], 1);
    g_csr[pos] = make_int2(dst, __float_as_int(w));
}

// ---------------------------------------------------------------------------
// K8: aggregate per node (one warp per node, 4-wide unrolled gather)
// ---------------------------------------------------------------------------
__global__ __launch_bounds__(256) void aggregate_kernel(float* __restrict__ out) {
    const int node = (blockIdx.x * blockDim.x + threadIdx.x) >> 5;
    const int lane = threadIdx.x & 31;
    if (node >= N_NODES) return;

    const int start = g_rowptr[node];
    const int deg   = g_deg[node];
    const int end   = start + deg;

    float4 acc = make_float4(0.f, 0.f, 0.f, 0.f);
    float wsum = 0.f;

    int e = start;
    for (; e + 4 <= end; e += 4) {
        int2 r0 = g_csr[e], r1 = g_csr[e + 1], r2 = g_csr[e + 2], r3 = g_csr[e + 3];
        float w0 = __int_as_float(r0.y), w1 = __int_as_float(r1.y);
        float w2 = __int_as_float(r2.y), w3 = __int_as_float(r3.y);
        float4 v0 = *(const float4*)(g_h + (size_t)r0.x * OUT_DIM + lane * 4);
        float4 v1 = *(const float4*)(g_h + (size_t)r1.x * OUT_DIM + lane * 4);
        float4 v2 = *(const float4*)(g_h + (size_t)r2.x * OUT_DIM + lane * 4);
        float4 v3 = *(const float4*)(g_h + (size_t)r3.x * OUT_DIM + lane * 4);
        acc.x += w0 * v0.x + w1 * v1.x + w2 * v2.x + w3 * v3.x;
        acc.y += w0 * v0.y + w1 * v1.y + w2 * v2.y + w3 * v3.y;
        acc.z += w0 * v0.z + w1 * v1.z + w2 * v2.z + w3 * v3.z;
        acc.w += w0 * v0.w + w1 * v1.w + w2 * v2.w + w3 * v3.w;
        wsum  += w0 + w1 + w2 + w3;
    }
    for (; e < end; e++) {
        int2 r = g_csr[e];
        const float w = __int_as_float(r.y);
        float4 v = *(const float4*)(g_h + (size_t)r.x * OUT_DIM + lane * 4);
        acc.x += w * v.x; acc.y += w * v.y; acc.z += w * v.z; acc.w += w * v.w;
        wsum  += w;
    }

    const float inv = 1.0f / (wsum + EPS);
    acc.x *= inv; acc.y *= inv; acc.z *= inv; acc.w *= inv;
    acc.x = (acc.x > 0.f) ? acc.x : ALPHA * acc.x;
    acc.y = (acc.y > 0.f) ? acc.y : ALPHA * acc.y;
    acc.z = (acc.z > 0.f) ? acc.z : ALPHA * acc.z;
    acc.w = (acc.w > 0.f) ? acc.w : ALPHA * acc.w;
    *(float4*)(out + (size_t)node * OUT_DIM + lane * 4) = acc;
}

// ---------------------------------------------------------------------------
extern "C" void kernel_launch(void* const* d_in, const int* in_sizes, int n_in,
                              void* d_out, int out_size) {
    const float* x    = (const float*)d_in[0];
    const void*  ei   = d_in[1];
    const float* W    = (const float*)d_in[2];
    const float* attn = (const float*)d_in[3];
    float*       out  = (float*)d_out;

    const int n_edges = in_sizes[1] / 2;

    cudaFuncSetAttribute(gemm_mma_kernel, cudaFuncAttributeMaxDynamicSharedMemorySize, GEMM_SMEM);

    zero_kernel<<<(N_NODES + 255) / 256, 256>>>();
    probe_kernel<<<16, 256>>>(ei, in_sizes[1]);
    convert_hist_kernel<<<(n_edges + 255) / 256, 256>>>(ei, n_edges);
    prep_w_kernel<<<(IN_DIM * OUT_DIM + 255) / 256, 256>>>(W);
    gemm_mma_kernel<<<(N_NODES + 127) / 128, 256, GEMM_SMEM>>>(x);
    score_kernel<<<(N_NODES * 32 + 255) / 256, 256>>>(attn);
    scan_kernel<<<1, 1024>>>();
    scatter_kernel<<<(n_edges + 255) / 256, 256>>>(n_edges);
    aggregate_kernel<<<(N_NODES * 32 + 255) / 256, 256>>>(out);
}

// round 10
// speedup vs baseline: 1.1105x; 1.0536x over previous
#include <cuda_runtime.h>
#include <cuda_bf16.h>
#include <cuda_fp16.h>
#include <cstdint>

#define N_NODES 100000
#define N_EDGES_MAX 3300000
#define IN_DIM  256
#define OUT_DIM 128
#define ALPHA   0.1f
#define EPS     9e-15f

// ---------------- scratch (device globals; no runtime allocation) ----------
__device__ __align__(16) float g_h[(size_t)N_NODES * OUT_DIM];      // fp32 h (scores)
__device__ __align__(16) __half g_h2[(size_t)N_NODES * OUT_DIM];    // fp16 h (aggregate)
__device__ __align__(16) float g_score_l[N_NODES];
__device__ __align__(16) float g_score_r[N_NODES];
__device__ __align__(16) __nv_bfloat16 g_wt_hi[OUT_DIM * IN_DIM]; // W^T hi  [n][k]
__device__ __align__(16) __nv_bfloat16 g_wt_lo[OUT_DIM * IN_DIM]; // W^T lo
__device__ int   g_src[N_EDGES_MAX];
__device__ int   g_dst[N_EDGES_MAX];
__device__ int   g_deg[N_NODES];
__device__ int   g_rowptr[N_NODES];
__device__ int   g_cursor[N_NODES];
__device__ __align__(16) int2 g_csr[N_EDGES_MAX];   // packed (dst, w-bits)
__device__ int   g_is64;

__device__ __forceinline__ uint32_t pack2bf16(float x, float y) {
    __nv_bfloat16 hx = __float2bfloat16(x), hy = __float2bfloat16(y);
    uint16_t a = *reinterpret_cast<uint16_t*>(&hx);
    uint16_t b = *reinterpret_cast<uint16_t*>(&hy);
    return (uint32_t)a | ((uint32_t)b << 16);
}
__device__ __forceinline__ uint32_t pack2half(float x, float y) {
    __half2 h = __floats2half2_rn(x, y);
    return *reinterpret_cast<uint32_t*>(&h);
}

// ---------------------------------------------------------------------------
// K0: zero degree histogram + reset dtype flag
// ---------------------------------------------------------------------------
__global__ void zero_kernel() {
    int i = blockIdx.x * blockDim.x + threadIdx.x;
    if (i < N_NODES) g_deg[i] = 0;
    if (i == 0) g_is64 = 1;
}
// K1: probe dtype (int64 vs int32 delivery)
__global__ void probe_kernel(const void* ei, int n_elems64) {
    const long long* p = (const long long*)ei;
    int i = threadIdx.x + blockIdx.x * blockDim.x;
    int K = n_elems64 < 4096 ? n_elems64 : 4096;
    if (i < K) {
        long long v = p[i];
        if (v < 0 || v >= N_NODES) atomicAnd(&g_is64, 0);
    }
}

// K2: convert edge list + histogram degrees by src
__global__ __launch_bounds__(256) void convert_hist_kernel(const void* __restrict__ ei_raw,
                                                           const int n_edges) {
    int i = blockIdx.x * blockDim.x + threadIdx.x;
    if (i >= n_edges) return;
    int src, dst;
    if (g_is64) {
        const long long* ei = (const long long*)ei_raw;
        src = (int)ei[i];
        dst = (int)ei[(size_t)n_edges + i];
    } else {
        const int* ei = (const int*)ei_raw;
        src = ei[i];
        dst = ei[(size_t)n_edges + i];
    }
    g_src[i] = src;
    g_dst[i] = dst;
    if ((unsigned)src < N_NODES && (unsigned)dst < N_NODES)
        atomicAdd(&g_deg[src], 1);
}

// K3: W^T split into bf16 hi/lo  (Wt[n][k] = W[k][n])
__global__ __launch_bounds__(256) void prep_w_kernel(const float* __restrict__ W) {
    int i = blockIdx.x * blockDim.x + threadIdx.x;
    if (i >= IN_DIM * OUT_DIM) return;
    int n = i % OUT_DIM;
    int k = i / OUT_DIM;
    float w = W[(size_t)k * OUT_DIM + n];
    __nv_bfloat16 hi = __float2bfloat16(w);
    float lo = w - __bfloat162float(hi);
    g_wt_hi[(size_t)n * IN_DIM + k] = hi;
    g_wt_lo[(size_t)n * IN_DIM + k] = __float2bfloat16(lo);
}

// ---------------------------------------------------------------------------
// K4: mma.sync bf16 GEMM  H = X @ W  (3-term bf16 split, fp32 accum)
//   CTA tile 128x128, K in 4 chunks of 64.  Epilogue emits fp32 H + fp16 H2.
// ---------------------------------------------------------------------------
#define KCHUNK 64
#define ROW_W   72                       // bf16 per padded row
#define TILE_B  (128 * ROW_W * 2)        // 18432 bytes per tile
#define GEMM_SMEM (4 * TILE_B)

__device__ __forceinline__ void mma16816(float* c, const uint32_t* a, const uint32_t* b) {
    asm volatile(
        "mma.sync.aligned.m16n8k16.row.col.f32.bf16.bf16.f32 "
        "{%0,%1,%2,%3}, {%4,%5,%6,%7}, {%8,%9}, {%0,%1,%2,%3};"
        : "+f"(c[0]), "+f"(c[1]), "+f"(c[2]), "+f"(c[3])
        : "r"(a[0]), "r"(a[1]), "r"(a[2]), "r"(a[3]), "r"(b[0]), "r"(b[1]));
}

__global__ __launch_bounds__(256, 2)
void gemm_mma_kernel(const float* __restrict__ X) {
    extern __shared__ __align__(16) char smem_raw[];
    __nv_bfloat16* sAh = (__nv_bfloat16*)(smem_raw);
    __nv_bfloat16* sAl = (__nv_bfloat16*)(smem_raw + TILE_B);
    __nv_bfloat16* sBh = (__nv_bfloat16*)(smem_raw + 2 * TILE_B);
    __nv_bfloat16* sBl = (__nv_bfloat16*)(smem_raw + 3 * TILE_B);

    const int tid  = threadIdx.x;
    const int wid  = tid >> 5;
    const int lane = tid & 31;
    const int g    = lane >> 2;     // 0..7
    const int t    = lane & 3;      // 0..3
    const int wm   = wid >> 2;      // 0..1  (m warp)
    const int wn   = wid & 3;       // 0..3  (n warp)
    const int block_row = blockIdx.x * 128;

    float acc[4][4][4];
    #pragma unroll
    for (int i = 0; i < 4; i++)
        #pragma unroll
        for (int j = 0; j < 4; j++)
            #pragma unroll
            for (int r = 0; r < 4; r++) acc[i][j][r] = 0.f;

    for (int kc = 0; kc < IN_DIM / KCHUNK; kc++) {
        // ---- load + split X chunk (128 rows x 64 cols): 1024 units of 8 cols
        #pragma unroll
        for (int u = 0; u < 4; u++) {
            const int unit = tid + 256 * u;
            const int row  = unit >> 3;
            const int c8   = (unit & 7) * 8;
            const int gr   = block_row + row;
            float4 v0 = make_float4(0.f, 0.f, 0.f, 0.f);
            float4 v1 = make_float4(0.f, 0.f, 0.f, 0.f);
            if (gr < N_NODES) {
                const float* xp = X + (size_t)gr * IN_DIM + kc * KCHUNK + c8;
                v0 = *(const float4*)(xp);
                v1 = *(const float4*)(xp + 4);
            }
            uint4 hi, lo;
            {
                __nv_bfloat16 h0 = __float2bfloat16(v0.x), h1 = __float2bfloat16(v0.y);
                __nv_bfloat16 h2 = __float2bfloat16(v0.z), h3 = __float2bfloat16(v0.w);
                __nv_bfloat16 h4 = __float2bfloat16(v1.x), h5 = __float2bfloat16(v1.y);
                __nv_bfloat16 h6 = __float2bfloat16(v1.z), h7 = __float2bfloat16(v1.w);
                hi.x = ((uint32_t)*(uint16_t*)&h0) | ((uint32_t)*(uint16_t*)&h1 << 16);
                hi.y = ((uint32_t)*(uint16_t*)&h2) | ((uint32_t)*(uint16_t*)&h3 << 16);
                hi.z = ((uint32_t)*(uint16_t*)&h4) | ((uint32_t)*(uint16_t*)&h5 << 16);
                hi.w = ((uint32_t)*(uint16_t*)&h6) | ((uint32_t)*(uint16_t*)&h7 << 16);
                lo.x = pack2bf16(v0.x - __bfloat162float(h0), v0.y - __bfloat162float(h1));
                lo.y = pack2bf16(v0.z - __bfloat162float(h2), v0.w - __bfloat162float(h3));
                lo.z = pack2bf16(v1.x - __bfloat162float(h4), v1.y - __bfloat162float(h5));
                lo.w = pack2bf16(v1.z - __bfloat162float(h6), v1.w - __bfloat162float(h7));
            }
            *(uint4*)(sAh + row * ROW_W + c8) = hi;
            *(uint4*)(sAl + row * ROW_W + c8) = lo;
        }
        // ---- load B chunk (Wt hi/lo, 128 n-rows x 64 k)
        #pragma unroll
        for (int u = 0; u < 4; u++) {
            const int unit = tid + 256 * u;
            const int n    = unit >> 3;
            const int c8   = (unit & 7) * 8;
            const size_t gofs = (size_t)n * IN_DIM + kc * KCHUNK + c8;
            *(uint4*)(sBh + n * ROW_W + c8) = *(const uint4*)(g_wt_hi + gofs);
            *(uint4*)(sBl + n * ROW_W + c8) = *(const uint4*)(g_wt_lo + gofs);
        }
        __syncthreads();

        const uint32_t* Ah = (const uint32_t*)sAh;
        const uint32_t* Al = (const uint32_t*)sAl;
        const uint32_t* Bh = (const uint32_t*)sBh;
        const uint32_t* Bl = (const uint32_t*)sBl;
        const int RW = ROW_W / 2;   // 36 words per row

        #define DO_TERM(Ap, Bp)                                                        \
        {                                                                              \
            _Pragma("unroll")                                                          \
            for (int ks = 0; ks < 4; ks++) {                                           \
                uint32_t afr[4][4];                                                    \
                _Pragma("unroll")                                                      \
                for (int mt = 0; mt < 4; mt++) {                                       \
                    const int row = wm * 64 + mt * 16 + g;                             \
                    afr[mt][0] = Ap[row * RW + ks * 8 + t];                            \
                    afr[mt][1] = Ap[(row + 8) * RW + ks * 8 + t];                      \
                    afr[mt][2] = Ap[row * RW + ks * 8 + t + 4];                        \
                    afr[mt][3] = Ap[(row + 8) * RW + ks * 8 + t + 4];                  \
                }                                                                      \
                uint32_t bfr[4][2];                                                    \
                _Pragma("unroll")                                                      \
                for (int nt = 0; nt < 4; nt++) {                                       \
                    const int nr = wn * 32 + nt * 8 + g;                               \
                    bfr[nt][0] = Bp[nr * RW + ks * 8 + t];                             \
                    bfr[nt][1] = Bp[nr * RW + ks * 8 + t + 4];                         \
                }                                                                      \
                _Pragma("unroll")                                                      \
                for (int mt = 0; mt < 4; mt++)                                         \
                    _Pragma("unroll")                                                  \
                    for (int nt = 0; nt < 4; nt++)                                     \
                        mma16816(acc[mt][nt], afr[mt], bfr[nt]);                       \
            }                                                                          \
        }

        DO_TERM(Ah, Bh);
        DO_TERM(Ah, Bl);
        DO_TERM(Al, Bh);
        #undef DO_TERM
        __syncthreads();
    }

    // ---- epilogue: write fp32 H and fp16 H2
    #pragma unroll
    for (int mt = 0; mt < 4; mt++) {
        const int r0 = block_row + wm * 64 + mt * 16 + g;
        const int r1 = r0 + 8;
        #pragma unroll
        for (int nt = 0; nt < 4; nt++) {
            const int col = wn * 32 + nt * 8 + 2 * t;
            if (r0 < N_NODES) {
                *(float2*)(g_h + (size_t)r0 * OUT_DIM + col) = make_float2(acc[mt][nt][0], acc[mt][nt][1]);
                *(uint32_t*)(g_h2 + (size_t)r0 * OUT_DIM + col) = pack2half(acc[mt][nt][0], acc[mt][nt][1]);
            }
            if (r1 < N_NODES) {
                *(float2*)(g_h + (size_t)r1 * OUT_DIM + col) = make_float2(acc[mt][nt][2], acc[mt][nt][3]);
                *(uint32_t*)(g_h2 + (size_t)r1 * OUT_DIM + col) = pack2half(acc[mt][nt][2], acc[mt][nt][3]);
            }
        }
    }
}

// ---------------------------------------------------------------------------
// K5: per-node attention scores  (one warp per node, fp32 h)
// ---------------------------------------------------------------------------
__global__ __launch_bounds__(256) void score_kernel(const float* __restrict__ attn) {
    const int warp = (blockIdx.x * blockDim.x + threadIdx.x) >> 5;
    const int lane = threadIdx.x & 31;
    if (warp >= N_NODES) return;

    float4 hv = *(const float4*)(g_h + (size_t)warp * OUT_DIM + lane * 4);
    float4 al = *(const float4*)(attn + lane * 4);
    float4 ar = *(const float4*)(attn + OUT_DIM + lane * 4);

    float dl = hv.x * al.x + hv.y * al.y + hv.z * al.z + hv.w * al.w;
    float dr = hv.x * ar.x + hv.y * ar.y + hv.z * ar.z + hv.w * ar.w;

    #pragma unroll
    for (int off = 16; off > 0; off >>= 1) {
        dl += __shfl_xor_sync(0xffffffff, dl, off);
        dr += __shfl_xor_sync(0xffffffff, dr, off);
    }
    if (lane == 0) {
        g_score_l[warp] = dl;
        g_score_r[warp] = dr;
    }
}

// ---------------------------------------------------------------------------
// K6: exclusive scan of degrees -> rowptr, cursor
// ---------------------------------------------------------------------------
__global__ __launch_bounds__(1024) void scan_kernel() {
    __shared__ int sh[1024];
    const int t = threadIdx.x;
    const int CHUNK = (N_NODES + 1023) / 1024;
    const int lo = t * CHUNK;
    const int hi = min(lo + CHUNK, N_NODES);

    int s = 0;
    for (int i = lo; i < hi; i++) s += g_deg[i];
    sh[t] = s;
    __syncthreads();
    for (int off = 1; off < 1024; off <<= 1) {
        int v = (t >= off) ? sh[t - off] : 0;
        __syncthreads();
        sh[t] += v;
        __syncthreads();
    }
    int run = sh[t] - s;
    for (int i = lo; i < hi; i++) {
        g_rowptr[i] = run;
        g_cursor[i] = run;
        run += g_deg[i];
    }
}

// ---------------------------------------------------------------------------
// K7: scatter edges into CSR (packed int2 record) with softmax weights
// ---------------------------------------------------------------------------
__global__ __launch_bounds__(256) void scatter_kernel(const int n_edges) {
    int i = blockIdx.x * blockDim.x + threadIdx.x;
    if (i >= n_edges) return;
    const int src = g_src[i];
    const int dst = g_dst[i];
    if ((unsigned)src >= N_NODES || (unsigned)dst >= N_NODES) return;

    float s = g_score_l[src] + g_score_r[dst];
    s = (s > 0.f) ? s : ALPHA * s;
    const float w = __expf(s);

    const int pos = atomicAdd(&g_cursor[src], 1);
    g_csr[pos] = make_int2(dst, __float_as_int(w));
}

// ---------------------------------------------------------------------------
// K8: aggregate per node (one warp per node, fp16 h gather, fp32 accum)
// ---------------------------------------------------------------------------
__global__ __launch_bounds__(256) void aggregate_kernel(float* __restrict__ out) {
    const int node = (blockIdx.x * blockDim.x + threadIdx.x) >> 5;
    const int lane = threadIdx.x & 31;
    if (node >= N_NODES) return;

    const int start = g_rowptr[node];
    const int deg   = g_deg[node];
    const int end   = start + deg;

    float4 acc = make_float4(0.f, 0.f, 0.f, 0.f);
    float wsum = 0.f;

    int e = start;
    for (; e + 4 <= end; e += 4) {
        int2 r0 = g_csr[e], r1 = g_csr[e + 1], r2 = g_csr[e + 2], r3 = g_csr[e + 3];
        float w0 = __int_as_float(r0.y), w1 = __int_as_float(r1.y);
        float w2 = __int_as_float(r2.y), w3 = __int_as_float(r3.y);
        uint2 p0 = *(const uint2*)(g_h2 + (size_t)r0.x * OUT_DIM + lane * 4);
        uint2 p1 = *(const uint2*)(g_h2 + (size_t)r1.x * OUT_DIM + lane * 4);
        uint2 p2 = *(const uint2*)(g_h2 + (size_t)r2.x * OUT_DIM + lane * 4);
        uint2 p3 = *(const uint2*)(g_h2 + (size_t)r3.x * OUT_DIM + lane * 4);
        float2 a0 = __half22float2(*reinterpret_cast<__half2*>(&p0.x));
        float2 b0 = __half22float2(*reinterpret_cast<__half2*>(&p0.y));
        float2 a1 = __half22float2(*reinterpret_cast<__half2*>(&p1.x));
        float2 b1 = __half22float2(*reinterpret_cast<__half2*>(&p1.y));
        float2 a2 = __half22float2(*reinterpret_cast<__half2*>(&p2.x));
        float2 b2 = __half22float2(*reinterpret_cast<__half2*>(&p2.y));
        float2 a3 = __half22float2(*reinterpret_cast<__half2*>(&p3.x));
        float2 b3 = __half22float2(*reinterpret_cast<__half2*>(&p3.y));
        acc.x += w0 * a0.x + w1 * a1.x + w2 * a2.x + w3 * a3.x;
        acc.y += w0 * a0.y + w1 * a1.y + w2 * a2.y + w3 * a3.y;
        acc.z += w0 * b0.x + w1 * b1.x + w2 * b2.x + w3 * b3.x;
        acc.w += w0 * b0.y + w1 * b1.y + w2 * b2.y + w3 * b3.y;
        wsum  += w0 + w1 + w2 + w3;
    }
    for (; e < end; e++) {
        int2 r = g_csr[e];
        const float w = __int_as_float(r.y);
        uint2 p = *(const uint2*)(g_h2 + (size_t)r.x * OUT_DIM + lane * 4);
        float2 a = __half22float2(*reinterpret_cast<__half2*>(&p.x));
        float2 b = __half22float2(*reinterpret_cast<__half2*>(&p.y));
        acc.x += w * a.x; acc.y += w * a.y; acc.z += w * b.x; acc.w += w * b.y;
        wsum  += w;
    }

    const float inv = 1.0f / (wsum + EPS);
    acc.x *= inv; acc.y *= inv; acc.z *= inv; acc.w *= inv;
    acc.x = (acc.x > 0.f) ? acc.x : ALPHA * acc.x;
    acc.y = (acc.y > 0.f) ? acc.y : ALPHA * acc.y;
    acc.z = (acc.z > 0.f) ? acc.z : ALPHA * acc.z;
    acc.w = (acc.w > 0.f) ? acc.w : ALPHA * acc.w;
    *(float4*)(out + (size_t)node * OUT_DIM + lane * 4) = acc;
}

// ---------------------------------------------------------------------------
extern "C" void kernel_launch(void* const* d_in, const int* in_sizes, int n_in,
                              void* d_out, int out_size) {
    const float* x    = (const float*)d_in[0];
    const void*  ei   = d_in[1];
    const float* W    = (const float*)d_in[2];
    const float* attn = (const float*)d_in[3];
    float*       out  = (float*)d_out;

    const int n_edges = in_sizes[1] / 2;

    cudaFuncSetAttribute(gemm_mma_kernel, cudaFuncAttributeMaxDynamicSharedMemorySize, GEMM_SMEM);

    zero_kernel<<<(N_NODES + 255) / 256, 256>>>();
    probe_kernel<<<16, 256>>>(ei, in_sizes[1]);
    convert_hist_kernel<<<(n_edges + 255) / 256, 256>>>(ei, n_edges);
    prep_w_kernel<<<(IN_DIM * OUT_DIM + 255) / 256, 256>>>(W);
    gemm_mma_kernel<<<(N_NODES + 127) / 128, 256, GEMM_SMEM>>>(x);
    score_kernel<<<(N_NODES * 32 + 255) / 256, 256>>>(attn);
    scan_kernel<<<1, 1024>>>();
    scatter_kernel<<<(n_edges + 255) / 256, 256>>>(n_edges);
    aggregate_kernel<<<(N_NODES * 32 + 255) / 256, 256>>>(out);
}

// round 11
// speedup vs baseline: 1.1356x; 1.0226x over previous
#include <cuda_runtime.h>
#include <cuda_bf16.h>
#include <cuda_fp16.h>
#include <cstdint>

#define N_NODES 100000
#define N_EDGES_MAX 3300000
#define IN_DIM  256
#define OUT_DIM 128
#define ALPHA   0.1f
#define EPS     9e-15f

// ---------------- scratch (device globals; no runtime allocation) ----------
__device__ __align__(16) __half g_h2[(size_t)N_NODES * OUT_DIM];    // fp16 h (25.6 MB)
__device__ __align__(16) float g_score_l[N_NODES];
__device__ __align__(16) float g_score_r[N_NODES];
__device__ __align__(16) __nv_bfloat16 g_wt_hi[OUT_DIM * IN_DIM]; // W^T hi  [n][k]
__device__ __align__(16) __nv_bfloat16 g_wt_lo[OUT_DIM * IN_DIM]; // W^T lo
__device__ int   g_src[N_EDGES_MAX];
__device__ int   g_dst[N_EDGES_MAX];
__device__ int   g_deg[N_NODES];
__device__ int   g_rowptr[N_NODES];
__device__ int   g_cursor[N_NODES];
__device__ __align__(16) int2 g_csr[N_EDGES_MAX];   // packed (dst, w-bits)
__device__ int   g_is64;

__device__ __forceinline__ uint32_t pack2bf16(float x, float y) {
    __nv_bfloat16 hx = __float2bfloat16(x), hy = __float2bfloat16(y);
    uint16_t a = *reinterpret_cast<uint16_t*>(&hx);
    uint16_t b = *reinterpret_cast<uint16_t*>(&hy);
    return (uint32_t)a | ((uint32_t)b << 16);
}
__device__ __forceinline__ uint32_t pack2half(float x, float y) {
    __half2 h = __floats2half2_rn(x, y);
    return *reinterpret_cast<uint32_t*>(&h);
}

// ---------------------------------------------------------------------------
// K0: zero degree histogram + reset dtype flag
// ---------------------------------------------------------------------------
__global__ void zero_kernel() {
    int i = blockIdx.x * blockDim.x + threadIdx.x;
    if (i < N_NODES) g_deg[i] = 0;
    if (i == 0) g_is64 = 1;
}
// K1: probe dtype (int64 vs int32 delivery)
__global__ void probe_kernel(const void* ei, int n_elems64) {
    const long long* p = (const long long*)ei;
    int i = threadIdx.x + blockIdx.x * blockDim.x;
    int K = n_elems64 < 4096 ? n_elems64 : 4096;
    if (i < K) {
        long long v = p[i];
        if (v < 0 || v >= N_NODES) atomicAnd(&g_is64, 0);
    }
}

// K2: convert edge list + histogram degrees by src
__global__ __launch_bounds__(256) void convert_hist_kernel(const void* __restrict__ ei_raw,
                                                           const int n_edges) {
    int i = blockIdx.x * blockDim.x + threadIdx.x;
    if (i >= n_edges) return;
    int src, dst;
    if (g_is64) {
        const long long* ei = (const long long*)ei_raw;
        src = (int)ei[i];
        dst = (int)ei[(size_t)n_edges + i];
    } else {
        const int* ei = (const int*)ei_raw;
        src = ei[i];
        dst = ei[(size_t)n_edges + i];
    }
    g_src[i] = src;
    g_dst[i] = dst;
    if ((unsigned)src < N_NODES && (unsigned)dst < N_NODES)
        atomicAdd(&g_deg[src], 1);
}

// K3: W^T split into bf16 hi/lo  (Wt[n][k] = W[k][n])
__global__ __launch_bounds__(256) void prep_w_kernel(const float* __restrict__ W) {
    int i = blockIdx.x * blockDim.x + threadIdx.x;
    if (i >= IN_DIM * OUT_DIM) return;
    int n = i % OUT_DIM;
    int k = i / OUT_DIM;
    float w = W[(size_t)k * OUT_DIM + n];
    __nv_bfloat16 hi = __float2bfloat16(w);
    float lo = w - __bfloat162float(hi);
    g_wt_hi[(size_t)n * IN_DIM + k] = hi;
    g_wt_lo[(size_t)n * IN_DIM + k] = __float2bfloat16(lo);
}

// ---------------------------------------------------------------------------
// K4: mma.sync bf16 GEMM  H = X @ W  (3-term bf16 split, fp32 accum)
//   CTA tile 128x128, K in 4 chunks of 64.  Epilogue emits fp16 H2 only.
// ---------------------------------------------------------------------------
#define KCHUNK 64
#define ROW_W   72                       // bf16 per padded row
#define TILE_B  (128 * ROW_W * 2)        // 18432 bytes per tile
#define GEMM_SMEM (4 * TILE_B)

__device__ __forceinline__ void mma16816(float* c, const uint32_t* a, const uint32_t* b) {
    asm volatile(
        "mma.sync.aligned.m16n8k16.row.col.f32.bf16.bf16.f32 "
        "{%0,%1,%2,%3}, {%4,%5,%6,%7}, {%8,%9}, {%0,%1,%2,%3};"
        : "+f"(c[0]), "+f"(c[1]), "+f"(c[2]), "+f"(c[3])
        : "r"(a[0]), "r"(a[1]), "r"(a[2]), "r"(a[3]), "r"(b[0]), "r"(b[1]));
}

__global__ __launch_bounds__(256, 2)
void gemm_mma_kernel(const float* __restrict__ X) {
    extern __shared__ __align__(16) char smem_raw[];
    __nv_bfloat16* sAh = (__nv_bfloat16*)(smem_raw);
    __nv_bfloat16* sAl = (__nv_bfloat16*)(smem_raw + TILE_B);
    __nv_bfloat16* sBh = (__nv_bfloat16*)(smem_raw + 2 * TILE_B);
    __nv_bfloat16* sBl = (__nv_bfloat16*)(smem_raw + 3 * TILE_B);

    const int tid  = threadIdx.x;
    const int wid  = tid >> 5;
    const int lane = tid & 31;
    const int g    = lane >> 2;     // 0..7
    const int t    = lane & 3;      // 0..3
    const int wm   = wid >> 2;      // 0..1  (m warp)
    const int wn   = wid & 3;       // 0..3  (n warp)
    const int block_row = blockIdx.x * 128;

    float acc[4][4][4];
    #pragma unroll
    for (int i = 0; i < 4; i++)
        #pragma unroll
        for (int j = 0; j < 4; j++)
            #pragma unroll
            for (int r = 0; r < 4; r++) acc[i][j][r] = 0.f;

    for (int kc = 0; kc < IN_DIM / KCHUNK; kc++) {
        // ---- load + split X chunk (128 rows x 64 cols): 1024 units of 8 cols
        #pragma unroll
        for (int u = 0; u < 4; u++) {
            const int unit = tid + 256 * u;
            const int row  = unit >> 3;
            const int c8   = (unit & 7) * 8;
            const int gr   = block_row + row;
            float4 v0 = make_float4(0.f, 0.f, 0.f, 0.f);
            float4 v1 = make_float4(0.f, 0.f, 0.f, 0.f);
            if (gr < N_NODES) {
                const float* xp = X + (size_t)gr * IN_DIM + kc * KCHUNK + c8;
                v0 = *(const float4*)(xp);
                v1 = *(const float4*)(xp + 4);
            }
            uint4 hi, lo;
            {
                __nv_bfloat16 h0 = __float2bfloat16(v0.x), h1 = __float2bfloat16(v0.y);
                __nv_bfloat16 h2 = __float2bfloat16(v0.z), h3 = __float2bfloat16(v0.w);
                __nv_bfloat16 h4 = __float2bfloat16(v1.x), h5 = __float2bfloat16(v1.y);
                __nv_bfloat16 h6 = __float2bfloat16(v1.z), h7 = __float2bfloat16(v1.w);
                hi.x = ((uint32_t)*(uint16_t*)&h0) | ((uint32_t)*(uint16_t*)&h1 << 16);
                hi.y = ((uint32_t)*(uint16_t*)&h2) | ((uint32_t)*(uint16_t*)&h3 << 16);
                hi.z = ((uint32_t)*(uint16_t*)&h4) | ((uint32_t)*(uint16_t*)&h5 << 16);
                hi.w = ((uint32_t)*(uint16_t*)&h6) | ((uint32_t)*(uint16_t*)&h7 << 16);
                lo.x = pack2bf16(v0.x - __bfloat162float(h0), v0.y - __bfloat162float(h1));
                lo.y = pack2bf16(v0.z - __bfloat162float(h2), v0.w - __bfloat162float(h3));
                lo.z = pack2bf16(v1.x - __bfloat162float(h4), v1.y - __bfloat162float(h5));
                lo.w = pack2bf16(v1.z - __bfloat162float(h6), v1.w - __bfloat162float(h7));
            }
            *(uint4*)(sAh + row * ROW_W + c8) = hi;
            *(uint4*)(sAl + row * ROW_W + c8) = lo;
        }
        // ---- load B chunk (Wt hi/lo, 128 n-rows x 64 k)
        #pragma unroll
        for (int u = 0; u < 4; u++) {
            const int unit = tid + 256 * u;
            const int n    = unit >> 3;
            const int c8   = (unit & 7) * 8;
            const size_t gofs = (size_t)n * IN_DIM + kc * KCHUNK + c8;
            *(uint4*)(sBh + n * ROW_W + c8) = *(const uint4*)(g_wt_hi + gofs);
            *(uint4*)(sBl + n * ROW_W + c8) = *(const uint4*)(g_wt_lo + gofs);
        }
        __syncthreads();

        const uint32_t* Ah = (const uint32_t*)sAh;
        const uint32_t* Al = (const uint32_t*)sAl;
        const uint32_t* Bh = (const uint32_t*)sBh;
        const uint32_t* Bl = (const uint32_t*)sBl;
        const int RW = ROW_W / 2;   // 36 words per row

        #define DO_TERM(Ap, Bp)                                                        \
        {                                                                              \
            _Pragma("unroll")                                                          \
            for (int ks = 0; ks < 4; ks++) {                                           \
                uint32_t afr[4][4];                                                    \
                _Pragma("unroll")                                                      \
                for (int mt = 0; mt < 4; mt++) {                                       \
                    const int row = wm * 64 + mt * 16 + g;                             \
                    afr[mt][0] = Ap[row * RW + ks * 8 + t];                            \
                    afr[mt][1] = Ap[(row + 8) * RW + ks * 8 + t];                      \
                    afr[mt][2] = Ap[row * RW + ks * 8 + t + 4];                        \
                    afr[mt][3] = Ap[(row + 8) * RW + ks * 8 + t + 4];                  \
                }                                                                      \
                uint32_t bfr[4][2];                                                    \
                _Pragma("unroll")                                                      \
                for (int nt = 0; nt < 4; nt++) {                                       \
                    const int nr = wn * 32 + nt * 8 + g;                               \
                    bfr[nt][0] = Bp[nr * RW + ks * 8 + t];                             \
                    bfr[nt][1] = Bp[nr * RW + ks * 8 + t + 4];                         \
                }                                                                      \
                _Pragma("unroll")                                                      \
                for (int mt = 0; mt < 4; mt++)                                         \
                    _Pragma("unroll")                                                  \
                    for (int nt = 0; nt < 4; nt++)                                     \
                        mma16816(acc[mt][nt], afr[mt], bfr[nt]);                       \
            }                                                                          \
        }

        DO_TERM(Ah, Bh);
        DO_TERM(Ah, Bl);
        DO_TERM(Al, Bh);
        #undef DO_TERM
        __syncthreads();
    }

    // ---- epilogue: write fp16 H2 only
    #pragma unroll
    for (int mt = 0; mt < 4; mt++) {
        const int r0 = block_row + wm * 64 + mt * 16 + g;
        const int r1 = r0 + 8;
        #pragma unroll
        for (int nt = 0; nt < 4; nt++) {
            const int col = wn * 32 + nt * 8 + 2 * t;
            if (r0 < N_NODES)
                *(uint32_t*)(g_h2 + (size_t)r0 * OUT_DIM + col) = pack2half(acc[mt][nt][0], acc[mt][nt][1]);
            if (r1 < N_NODES)
                *(uint32_t*)(g_h2 + (size_t)r1 * OUT_DIM + col) = pack2half(acc[mt][nt][2], acc[mt][nt][3]);
        }
    }
}

// ---------------------------------------------------------------------------
// K5: per-node attention scores  (one warp per node, fp16 h)
// ---------------------------------------------------------------------------
__global__ __launch_bounds__(256) void score_kernel(const float* __restrict__ attn) {
    const int warp = (blockIdx.x * blockDim.x + threadIdx.x) >> 5;
    const int lane = threadIdx.x & 31;
    if (warp >= N_NODES) return;

    uint2 p = *(const uint2*)(g_h2 + (size_t)warp * OUT_DIM + lane * 4);
    float2 a = __half22float2(*reinterpret_cast<__half2*>(&p.x));
    float2 b = __half22float2(*reinterpret_cast<__half2*>(&p.y));
    float4 al = *(const float4*)(attn + lane * 4);
    float4 ar = *(const float4*)(attn + OUT_DIM + lane * 4);

    float dl = a.x * al.x + a.y * al.y + b.x * al.z + b.y * al.w;
    float dr = a.x * ar.x + a.y * ar.y + b.x * ar.z + b.y * ar.w;

    #pragma unroll
    for (int off = 16; off > 0; off >>= 1) {
        dl += __shfl_xor_sync(0xffffffff, dl, off);
        dr += __shfl_xor_sync(0xffffffff, dr, off);
    }
    if (lane == 0) {
        g_score_l[warp] = dl;
        g_score_r[warp] = dr;
    }
}

// ---------------------------------------------------------------------------
// K6: exclusive scan of degrees -> rowptr, cursor
// ---------------------------------------------------------------------------
__global__ __launch_bounds__(1024) void scan_kernel() {
    __shared__ int sh[1024];
    const int t = threadIdx.x;
    const int CHUNK = (N_NODES + 1023) / 1024;
    const int lo = t * CHUNK;
    const int hi = min(lo + CHUNK, N_NODES);

    int s = 0;
    for (int i = lo; i < hi; i++) s += g_deg[i];
    sh[t] = s;
    __syncthreads();
    for (int off = 1; off < 1024; off <<= 1) {
        int v = (t >= off) ? sh[t - off] : 0;
        __syncthreads();
        sh[t] += v;
        __syncthreads();
    }
    int run = sh[t] - s;
    for (int i = lo; i < hi; i++) {
        g_rowptr[i] = run;
        g_cursor[i] = run;
        run += g_deg[i];
    }
}

// ---------------------------------------------------------------------------
// K7: scatter edges into CSR (packed int2 record) with softmax weights
// ---------------------------------------------------------------------------
__global__ __launch_bounds__(256) void scatter_kernel(const int n_edges) {
    int i = blockIdx.x * blockDim.x + threadIdx.x;
    if (i >= n_edges) return;
    const int src = g_src[i];
    const int dst = g_dst[i];
    if ((unsigned)src >= N_NODES || (unsigned)dst >= N_NODES) return;

    float s = g_score_l[src] + g_score_r[dst];
    s = (s > 0.f) ? s : ALPHA * s;
    const float w = __expf(s);

    const int pos = atomicAdd(&g_cursor[src], 1);
    g_csr[pos] = make_int2(dst, __float_as_int(w));
}

// ---------------------------------------------------------------------------
// K8: aggregate per node (one warp per node, fp16 h gather, fp32 accum)
// ---------------------------------------------------------------------------
__global__ __launch_bounds__(256) void aggregate_kernel(float* __restrict__ out) {
    const int node = (blockIdx.x * blockDim.x + threadIdx.x) >> 5;
    const int lane = threadIdx.x & 31;
    if (node >= N_NODES) return;

    const int start = g_rowptr[node];
    const int deg   = g_deg[node];
    const int end   = start + deg;

    float4 acc = make_float4(0.f, 0.f, 0.f, 0.f);
    float wsum = 0.f;

    int e = start;
    for (; e + 4 <= end; e += 4) {
        int2 r0 = g_csr[e], r1 = g_csr[e + 1], r2 = g_csr[e + 2], r3 = g_csr[e + 3];
        float w0 = __int_as_float(r0.y), w1 = __int_as_float(r1.y);
        float w2 = __int_as_float(r2.y), w3 = __int_as_float(r3.y);
        uint2 p0 = *(const uint2*)(g_h2 + (size_t)r0.x * OUT_DIM + lane * 4);
        uint2 p1 = *(const uint2*)(g_h2 + (size_t)r1.x * OUT_DIM + lane * 4);
        uint2 p2 = *(const uint2*)(g_h2 + (size_t)r2.x * OUT_DIM + lane * 4);
        uint2 p3 = *(const uint2*)(g_h2 + (size_t)r3.x * OUT_DIM + lane * 4);
        float2 a0 = __half22float2(*reinterpret_cast<__half2*>(&p0.x));
        float2 b0 = __half22float2(*reinterpret_cast<__half2*>(&p0.y));
        float2 a1 = __half22float2(*reinterpret_cast<__half2*>(&p1.x));
        float2 b1 = __half22float2(*reinterpret_cast<__half2*>(&p1.y));
        float2 a2 = __half22float2(*reinterpret_cast<__half2*>(&p2.x));
        float2 b2 = __half22float2(*reinterpret_cast<__half2*>(&p2.y));
        float2 a3 = __half22float2(*reinterpret_cast<__half2*>(&p3.x));
        float2 b3 = __half22float2(*reinterpret_cast<__half2*>(&p3.y));
        acc.x += w0 * a0.x + w1 * a1.x + w2 * a2.x + w3 * a3.x;
        acc.y += w0 * a0.y + w1 * a1.y + w2 * a2.y + w3 * a3.y;
        acc.z += w0 * b0.x + w1 * b1.x + w2 * b2.x + w3 * b3.x;
        acc.w += w0 * b0.y + w1 * b1.y + w2 * b2.y + w3 * b3.y;
        wsum  += w0 + w1 + w2 + w3;
    }
    for (; e < end; e++) {
        int2 r = g_csr[e];
        const float w = __int_as_float(r.y);
        uint2 p = *(const uint2*)(g_h2 + (size_t)r.x * OUT_DIM + lane * 4);
        float2 a = __half22float2(*reinterpret_cast<__half2*>(&p.x));
        float2 b = __half22float2(*reinterpret_cast<__half2*>(&p.y));
        acc.x += w * a.x; acc.y += w * a.y; acc.z += w * b.x; acc.w += w * b.y;
        wsum  += w;
    }

    const float inv = 1.0f / (wsum + EPS);
    acc.x *= inv; acc.y *= inv; acc.z *= inv; acc.w *= inv;
    acc.x = (acc.x > 0.f) ? acc.x : ALPHA * acc.x;
    acc.y = (acc.y > 0.f) ? acc.y : ALPHA * acc.y;
    acc.z = (acc.z > 0.f) ? acc.z : ALPHA * acc.z;
    acc.w = (acc.w > 0.f) ? acc.w : ALPHA * acc.w;
    *(float4*)(out + (size_t)node * OUT_DIM + lane * 4) = acc;
}

// ---------------------------------------------------------------------------
extern "C" void kernel_launch(void* const* d_in, const int* in_sizes, int n_in,
                              void* d_out, int out_size) {
    const float* x    = (const float*)d_in[0];
    const void*  ei   = d_in[1];
    const float* W    = (const float*)d_in[2];
    const float* attn = (const float*)d_in[3];
    float*       out  = (float*)d_out;

    const int n_edges = in_sizes[1] / 2;

    cudaFuncSetAttribute(gemm_mma_kernel, cudaFuncAttributeMaxDynamicSharedMemorySize, GEMM_SMEM);

    zero_kernel<<<(N_NODES + 255) / 256, 256>>>();
    probe_kernel<<<16, 256>>>(ei, in_sizes[1]);
    convert_hist_kernel<<<(n_edges + 255) / 256, 256>>>(ei, n_edges);
    prep_w_kernel<<<(IN_DIM * OUT_DIM + 255) / 256, 256>>>(W);
    gemm_mma_kernel<<<(N_NODES + 127) / 128, 256, GEMM_SMEM>>>(x);
    score_kernel<<<(N_NODES * 32 + 255) / 256, 256>>>(attn);
    scan_kernel<<<1, 1024>>>();
    scatter_kernel<<<(n_edges + 255) / 256, 256>>>(n_edges);
    aggregate_kernel<<<(N_NODES * 32 + 255) / 256, 256>>>(out);
}